// round 14
// baseline (speedup 1.0000x reference)
#include <cuda_runtime.h>

#define NROW 8
#define ROWN (1 << 20)          // elements per batch row
#define N4   (ROWN / 4)         // float4 count per row
#define NLOW 512                // low-bin histogram size (hot path)
#define PIVOT 0.25f             // bce < PIVOT -> histogram path
#define NBIN 2048               // full bins (fallback path only)
#define BPR  95                 // 760 blocks = 5/SM x 152 SMs, one wave
#define TPB  256
#define K_ALL 524288u           // max(1, int(N * 0.5))
#define SUMSCALE 4194304.0f     // 2^22 fixed-point scale for packed sums
#define INV_SUMSCALE 2.384185791015625e-7f   // 2^-22
#define CNT_SHIFT 44
#define SUM_MASK ((1ull << CNT_SHIFT) - 1ull)

// ---- global scratch (zero-initialized at load; tails restore zeros) ----
__device__ unsigned long long g_hist[NROW][NLOW];
__device__ float    g_sum_pos[NROW];
__device__ unsigned g_n_pos[NROW];
__device__ float    g_sum_hi[NROW];
__device__ unsigned g_n_hi[NROW];
__device__ unsigned g_row_done[NROW];
__device__ int      g_need_fb[NROW];
__device__ float    g_per[NROW];
__device__ unsigned g_rows_done;

// ---------------------------------------------------------------
// Single kernel. grid = (BPR, NROW), block = TPB.
//  - all blocks: streaming BCE; low-loss negatives -> tiny shared hist,
//    high-loss negatives -> register accumulators.
//  - per-row last block: resolve selection from low hist (hot path).
//  - global last block: O(1) flag check + final mean; full recompute
//    fallback only if some row was unresolved (cold, correctness-only).
// ---------------------------------------------------------------
__global__ __launch_bounds__(TPB, 5) void ohem_fused(
    const float* __restrict__ logits,
    const int*   __restrict__ targets,
    const int*   __restrict__ mask,
    float*       __restrict__ d_out)
{
    __shared__ unsigned long long s_hist[NBIN];   // main path uses [0,NLOW)
    __shared__ float    r_sp[TPB / 32], r_sh[TPB / 32];
    __shared__ unsigned r_np[TPB / 32], r_nh[TPB / 32];
    __shared__ unsigned s_wc[TPB / 32], s_wca[TPB / 32];
    __shared__ float    s_wf[TPB / 32], s_wfa[TPB / 32];
    __shared__ float    sh_kept;
    __shared__ unsigned sh_nlow;
    __shared__ int      sh_last, sh_glast, sh_fbany, sh_fb;

    const int row  = blockIdx.y;
    const int tid  = threadIdx.x;
    const int lane = tid & 31;
    const int wid  = tid >> 5;

    #pragma unroll
    for (int i = tid; i < NLOW; i += TPB) s_hist[i] = 0ull;
    __syncthreads();

    const float4* xl = (const float4*)(logits  + (size_t)row * ROWN);
    const int4*   tl = (const int4*)  (targets + (size_t)row * ROWN);
    const int4*   ml = (const int4*)  (mask    + (size_t)row * ROWN);

    float    sp = 0.f, sh = 0.f;
    unsigned np = 0u,  nh = 0u;

    const int stride = BPR * TPB;

    #pragma unroll 4
    for (int i = blockIdx.x * TPB + tid; i < N4; i += stride) {
        float4 x4 = xl[i];
        int4   t4 = tl[i];
        int4   m4 = ml[i];

        float xs[4] = {x4.x, x4.y, x4.z, x4.w};
        int   ts[4] = {t4.x, t4.y, t4.z, t4.w};
        int   ms[4] = {m4.x, m4.y, m4.z, m4.w};

        #pragma unroll
        for (int k = 0; k < 4; k++) {
            float x = xs[k];
            int   t = ts[k];          // {0,1}
            int   m = ms[k];          // {0,1}
            float s = __logf(1.f + __expf(-fabsf(x)));
            float xf = __int_as_float(__float_as_int(x) ^ (t << 31));
            float bce = s + fmaxf(xf, 0.f);   // == max(x,0)-x*t+log1p(exp(-|x|))

            int is_pos = m & t;
            int is_neg = m & (t ^ 1);
            sp += is_pos ? bce : 0.f;
            np += (unsigned)is_pos;

            int hi = is_neg & (bce >= PIVOT);
            sh += hi ? bce : 0.f;             // predicated, no atomic
            nh += (unsigned)hi;

            if (is_neg & (bce < PIVOT)) {     // rare (~2.6% of elements)
                unsigned bin = __float_as_uint(bce) >> 21;    // < 500
                unsigned long long pk = (1ull << CNT_SHIFT)
                    | (unsigned long long)(unsigned)(bce * SUMSCALE + 0.5f);
                atomicAdd(&s_hist[bin], pk);
            }
        }
    }

    // block reduce sp/np/sh/nh
    #pragma unroll
    for (int o = 16; o > 0; o >>= 1) {
        sp += __shfl_down_sync(0xffffffffu, sp, o);
        sh += __shfl_down_sync(0xffffffffu, sh, o);
        np += __shfl_down_sync(0xffffffffu, np, o);
        nh += __shfl_down_sync(0xffffffffu, nh, o);
    }
    if (lane == 0) { r_sp[wid] = sp; r_sh[wid] = sh; r_np[wid] = np; r_nh[wid] = nh; }
    __syncthreads();

    if (tid == 0) {
        float bsp = 0.f, bsh = 0.f; unsigned bnp = 0u, bnh = 0u;
        #pragma unroll
        for (int w = 0; w < TPB / 32; w++) {
            bsp += r_sp[w]; bsh += r_sh[w]; bnp += r_np[w]; bnh += r_nh[w];
        }
        atomicAdd(&g_sum_pos[row], bsp);
        atomicAdd(&g_sum_hi[row],  bsh);
        atomicAdd(&g_n_pos[row],   bnp);
        atomicAdd(&g_n_hi[row],    bnh);
    }

    // flush low histogram (sparse)
    for (int b = tid; b < NLOW; b += TPB) {
        unsigned long long v = s_hist[b];
        if (v) atomicAdd(&g_hist[row][b], v);
    }

    __threadfence();
    if (tid == 0) {
        unsigned old = atomicAdd(&g_row_done[row], 1u);
        sh_last = (old == BPR - 1) ? 1 : 0;
    }
    __syncthreads();
    if (!sh_last) return;

    // ============ per-row selection (last block of this row) ============
    __threadfence();   // acquire: see all blocks' hist/accumulator writes

    const unsigned np_row = g_n_pos[row];
    const float    sp_row = g_sum_pos[row];
    const unsigned nh_row = g_n_hi[row];
    const float    sh_row = g_sum_hi[row];

    {
        unsigned cnt2[2]; float sum2[2];
        unsigned csum = 0u; float fsum = 0.f;
        #pragma unroll
        for (int k = 0; k < 2; k++) {
            unsigned long long v = g_hist[row][tid * 2 + k];
            cnt2[k] = (unsigned)(v >> CNT_SHIFT);
            sum2[k] = (float)(v & SUM_MASK) * INV_SUMSCALE;
            csum += cnt2[k]; fsum += sum2[k];
        }

        unsigned ci = csum; float fi = fsum;
        #pragma unroll
        for (int off = 1; off < 32; off <<= 1) {
            unsigned c2 = __shfl_down_sync(0xffffffffu, ci, off);
            float    f2 = __shfl_down_sync(0xffffffffu, fi, off);
            if (lane + off < 32) { ci += c2; fi += f2; }
        }
        if (lane == 0) { s_wc[wid] = ci; s_wf[wid] = fi; }
        if (tid == 0) sh_kept = 0.f;
        __syncthreads();

        if (tid == 0) {
            unsigned ca = 0u; float sa = 0.f;
            for (int w = (TPB / 32) - 1; w >= 0; w--) {
                s_wca[w] = ca; s_wfa[w] = sa;
                ca += s_wc[w]; sa += s_wf[w];
            }
            sh_nlow = ca;
        }
        __syncthreads();

        const unsigned count_low = sh_nlow;
        const unsigned n_neg     = count_low + nh_row;
        const unsigned avail     = (K_ALL > np_row) ? (K_ALL - np_row) : 0u;
        const unsigned j         = (avail < n_neg) ? avail : n_neg;

        const int resolved = (j >= nh_row);
        const unsigned ju  = resolved ? (j - nh_row) : 0u;

        if (ju > 0u) {
            unsigned ca = s_wca[wid] + (ci - csum);
            float    sa = s_wfa[wid] + (fi - fsum);
            #pragma unroll
            for (int k = 1; k >= 0; k--) {
                unsigned c = cnt2[k];
                if (c && ca < ju && ca + c >= ju) {
                    float r    = (float)(ju - ca);
                    float mean = sum2[k] / (float)c;
                    sh_kept = sa + r * mean;
                }
                ca += c;
                sa += sum2[k];
            }
        }

        // cleanup this row for next graph replay
        #pragma unroll
        for (int k = 0; k < 2; k++) g_hist[row][tid * 2 + k] = 0ull;
        if (tid == 0) {
            g_sum_pos[row]  = 0.f;  g_n_pos[row] = 0u;
            g_sum_hi[row]   = 0.f;  g_n_hi[row]  = 0u;
            g_row_done[row] = 0u;
        }
        __syncthreads();

        if (tid == 0) {
            if (resolved) {
                float kkeep = (float)(np_row + j);
                float kept  = sh_row + sh_kept;
                g_per[row] = (kkeep > 0.f)
                           ? (sp_row + kept) / fmaxf(kkeep, 1.f) : 0.f;
                g_need_fb[row] = 0;
            } else {
                g_need_fb[row] = 1;   // cold path: global-last resolves
            }
        }
    }

    // ============ elect global-last block ============
    __threadfence();
    if (tid == 0) {
        unsigned old = atomicAdd(&g_rows_done, 1u);
        sh_glast = (old == NROW - 1) ? 1 : 0;
    }
    __syncthreads();
    if (!sh_glast) return;

    __threadfence();   // acquire: see all rows' g_per / g_need_fb

    // O(1) hot-path epilogue: one batched flag-read round, then mean.
    if (tid == 0) {
        int any = 0;
        #pragma unroll
        for (int r = 0; r < NROW; r++) any |= g_need_fb[r];   // independent loads
        sh_fbany = any;
    }
    __syncthreads();

    if (!sh_fbany) {
        if (tid == 0) {
            g_rows_done = 0u;
            float tot = 0.f;
            #pragma unroll
            for (int r = 0; r < NROW; r++) tot += g_per[r];
            d_out[0] = tot * (1.f / (float)NROW);
        }
        return;
    }

    // ---------- cold fallback: full recompute for flagged rows ----------
    for (int r = 0; r < NROW; r++) {
        if (tid == 0) sh_fb = g_need_fb[r];
        __syncthreads();
        if (!sh_fb) continue;

        for (int i = tid; i < NBIN; i += TPB) s_hist[i] = 0ull;
        __syncthreads();

        const float4* fxl = (const float4*)(logits  + (size_t)r * ROWN);
        const int4*   ftl = (const int4*)  (targets + (size_t)r * ROWN);
        const int4*   fml = (const int4*)  (mask    + (size_t)r * ROWN);

        float fsp = 0.f; unsigned fnp = 0u;
        for (int i = tid; i < N4; i += TPB) {
            float4 x4 = fxl[i]; int4 t4 = ftl[i]; int4 m4 = fml[i];
            float xs[4] = {x4.x, x4.y, x4.z, x4.w};
            int   ts[4] = {t4.x, t4.y, t4.z, t4.w};
            int   ms[4] = {m4.x, m4.y, m4.z, m4.w};
            #pragma unroll
            for (int k = 0; k < 4; k++) {
                float x = xs[k]; int t = ts[k]; int m = ms[k];
                float s = __logf(1.f + __expf(-fabsf(x)));
                float xf = __int_as_float(__float_as_int(x) ^ (t << 31));
                float bce = fmaxf(s + fmaxf(xf, 0.f), 0.f);
                if (m & t) { fsp += bce; fnp++; }
                if (m & (t ^ 1)) {
                    unsigned bin = __float_as_uint(bce) >> 21;
                    unsigned long long pk = (1ull << CNT_SHIFT)
                        | (unsigned long long)(unsigned)(bce * SUMSCALE + 0.5f);
                    atomicAdd(&s_hist[bin], pk);
                }
            }
        }
        #pragma unroll
        for (int o = 16; o > 0; o >>= 1) {
            fsp += __shfl_down_sync(0xffffffffu, fsp, o);
            fnp += __shfl_down_sync(0xffffffffu, fnp, o);
        }
        if (lane == 0) { r_sp[wid] = fsp; r_np[wid] = fnp; }
        __syncthreads();

        unsigned cnt8[8]; float sum8[8];
        unsigned csum = 0u; float fsum = 0.f;
        #pragma unroll
        for (int k = 0; k < 8; k++) {
            unsigned long long v = s_hist[tid * 8 + k];
            cnt8[k] = (unsigned)(v >> CNT_SHIFT);
            sum8[k] = (float)(v & SUM_MASK) * INV_SUMSCALE;
            csum += cnt8[k]; fsum += sum8[k];
        }
        unsigned ci = csum; float fi = fsum;
        #pragma unroll
        for (int off = 1; off < 32; off <<= 1) {
            unsigned c2 = __shfl_down_sync(0xffffffffu, ci, off);
            float    f2 = __shfl_down_sync(0xffffffffu, fi, off);
            if (lane + off < 32) { ci += c2; fi += f2; }
        }
        if (lane == 0) { s_wc[wid] = ci; s_wf[wid] = fi; }
        if (tid == 0) sh_kept = 0.f;
        __syncthreads();
        if (tid == 0) {
            unsigned ca = 0u; float sa = 0.f;
            for (int w = (TPB / 32) - 1; w >= 0; w--) {
                s_wca[w] = ca; s_wfa[w] = sa;
                ca += s_wc[w]; sa += s_wf[w];
            }
            sh_nlow = ca;   // total negatives
        }
        __syncthreads();

        __shared__ unsigned sh_np2;
        if (tid == 0) {
            float bsp = 0.f; unsigned bnp = 0u;
            #pragma unroll
            for (int w = 0; w < TPB / 32; w++) { bsp += r_sp[w]; bnp += r_np[w]; }
            r_sp[0] = bsp; sh_np2 = bnp;
        }
        __syncthreads();
        const unsigned npr   = sh_np2;
        const unsigned n_neg = sh_nlow;
        const unsigned avail = (K_ALL > npr) ? (K_ALL - npr) : 0u;
        const unsigned ju    = (avail < n_neg) ? avail : n_neg;

        if (ju > 0u) {
            unsigned ca = s_wca[wid] + (ci - csum);
            float    sa = s_wfa[wid] + (fi - fsum);
            #pragma unroll
            for (int k = 7; k >= 0; k--) {
                unsigned c = cnt8[k];
                if (c && ca < ju && ca + c >= ju) {
                    float rr   = (float)(ju - ca);
                    float mean = sum8[k] / (float)c;
                    sh_kept = sa + rr * mean;
                }
                ca += c;
                sa += sum8[k];
            }
        }
        __syncthreads();

        if (tid == 0) {
            float kkeep = (float)(npr + ju);
            g_per[r] = (kkeep > 0.f)
                     ? (r_sp[0] + sh_kept) / fmaxf(kkeep, 1.f) : 0.f;
            g_need_fb[r] = 0;
        }
        __syncthreads();
    }

    if (tid == 0) {
        g_rows_done = 0u;
        float tot = 0.f;
        #pragma unroll
        for (int r = 0; r < NROW; r++) tot += g_per[r];
        d_out[0] = tot * (1.f / (float)NROW);
    }
}

// ---------------------------------------------------------------
extern "C" void kernel_launch(void* const* d_in, const int* in_sizes, int n_in,
                              void* d_out, int out_size)
{
    (void)in_sizes; (void)n_in; (void)out_size;
    const float* logits  = (const float*)d_in[0];
    const int*   targets = (const int*)d_in[1];
    const int*   mask    = (const int*)d_in[2];
    float*       out     = (float*)d_out;

    dim3 grid(BPR, NROW);
    ohem_fused<<<grid, TPB>>>(logits, targets, mask, out);
}

// round 15
// speedup vs baseline: 1.1778x; 1.1778x over previous
#include <cuda_runtime.h>

#define NROW 8
#define ROWN (1 << 20)          // elements per batch row
#define N4   (ROWN / 4)         // float4 count per row
#define NLOW 512                // low-bin histogram size (hot path)
#define PIVOT 0.25f             // bce < PIVOT -> histogram path
#define NBIN 2048               // full bins (fallback path only)
#define BPR  114                // 912 blocks = 6/SM x 152 SMs, one wave
#define TPB  256
#define K_ALL 524288u           // max(1, int(N * 0.5))
#define SUMSCALE 4194304.0f     // 2^22 fixed-point scale for packed sums
#define INV_SUMSCALE 2.384185791015625e-7f   // 2^-22
#define CNT_SHIFT 44
#define SUM_MASK ((1ull << CNT_SHIFT) - 1ull)

// ---- global scratch (zero-initialized at load; tails restore zeros) ----
__device__ unsigned long long g_hist[NROW][NLOW];
__device__ unsigned long long g_fb_hist[NBIN];    // fallback only (cold)
__device__ float    g_sum_pos[NROW];
__device__ unsigned g_n_pos[NROW];
__device__ float    g_sum_all[NROW];   // sum of masked bce
__device__ unsigned g_n_mask[NROW];    // count of masked
__device__ unsigned g_row_done[NROW];
__device__ int      g_need_fb[NROW];
__device__ float    g_per[NROW];
__device__ unsigned g_rows_done;

// ---------------------------------------------------------------
// Single kernel. grid = (BPR, NROW), block = TPB.
// ---------------------------------------------------------------
__global__ __launch_bounds__(TPB, 6) void ohem_fused(
    const float* __restrict__ logits,
    const int*   __restrict__ targets,
    const int*   __restrict__ mask,
    float*       __restrict__ d_out)
{
    __shared__ unsigned long long s_hist[NLOW];
    __shared__ float    r_sp[TPB / 32], r_st[TPB / 32];
    __shared__ unsigned r_np[TPB / 32], r_nm[TPB / 32];
    __shared__ unsigned s_wc[TPB / 32], s_wca[TPB / 32];
    __shared__ float    s_wf[TPB / 32], s_wfa[TPB / 32];
    __shared__ float    sh_kept, sh_lowsum;
    __shared__ unsigned sh_nlow;
    __shared__ int      sh_last, sh_glast, sh_fbany, sh_fb;

    const int row  = blockIdx.y;
    const int tid  = threadIdx.x;
    const int lane = tid & 31;
    const int wid  = tid >> 5;

    #pragma unroll
    for (int i = tid; i < NLOW; i += TPB) s_hist[i] = 0ull;
    __syncthreads();

    const float4* xl = (const float4*)(logits  + (size_t)row * ROWN);
    const int4*   tl = (const int4*)  (targets + (size_t)row * ROWN);
    const int4*   ml = (const int4*)  (mask    + (size_t)row * ROWN);

    float    sp = 0.f, st = 0.f;
    unsigned np = 0u,  nm = 0u;

    const int stride = BPR * TPB;

    #pragma unroll 4
    for (int i = blockIdx.x * TPB + tid; i < N4; i += stride) {
        float4 x4 = xl[i];
        int4   t4 = tl[i];
        int4   m4 = ml[i];

        float xs[4] = {x4.x, x4.y, x4.z, x4.w};
        int   ts[4] = {t4.x, t4.y, t4.z, t4.w};
        int   ms[4] = {m4.x, m4.y, m4.z, m4.w};

        #pragma unroll
        for (int k = 0; k < 4; k++) {
            float x = xs[k];
            int   t = ts[k];          // {0,1}
            int   m = ms[k];          // {0,1}
            float s = __logf(1.f + __expf(-fabsf(x)));
            float xf = __int_as_float(__float_as_int(x) ^ (t << 31));
            float bce = s + fmaxf(xf, 0.f);   // == max(x,0)-x*t+log1p(exp(-|x|))

            int is_pos = m & t;
            st += m ? bce : 0.f;              // masked total (predicated)
            nm += (unsigned)m;
            sp += is_pos ? bce : 0.f;
            np += (unsigned)is_pos;

            if ((m & (t ^ 1)) && (bce < PIVOT)) {   // low-loss negative: rare
                unsigned bin = __float_as_uint(bce) >> 21;    // < 500
                unsigned long long pk = (1ull << CNT_SHIFT)
                    | (unsigned long long)(unsigned)(bce * SUMSCALE + 0.5f);
                atomicAdd(&s_hist[bin], pk);
            }
        }
    }

    // block reduce sp/np/st/nm
    #pragma unroll
    for (int o = 16; o > 0; o >>= 1) {
        sp += __shfl_down_sync(0xffffffffu, sp, o);
        st += __shfl_down_sync(0xffffffffu, st, o);
        np += __shfl_down_sync(0xffffffffu, np, o);
        nm += __shfl_down_sync(0xffffffffu, nm, o);
    }
    if (lane == 0) { r_sp[wid] = sp; r_st[wid] = st; r_np[wid] = np; r_nm[wid] = nm; }
    __syncthreads();

    if (tid == 0) {
        float bsp = 0.f, bst = 0.f; unsigned bnp = 0u, bnm = 0u;
        #pragma unroll
        for (int w = 0; w < TPB / 32; w++) {
            bsp += r_sp[w]; bst += r_st[w]; bnp += r_np[w]; bnm += r_nm[w];
        }
        atomicAdd(&g_sum_pos[row], bsp);
        atomicAdd(&g_sum_all[row], bst);
        atomicAdd(&g_n_pos[row],   bnp);
        atomicAdd(&g_n_mask[row],  bnm);
    }

    // flush low histogram (sparse)
    for (int b = tid; b < NLOW; b += TPB) {
        unsigned long long v = s_hist[b];
        if (v) atomicAdd(&g_hist[row][b], v);
    }

    __threadfence();
    if (tid == 0) {
        unsigned old = atomicAdd(&g_row_done[row], 1u);
        sh_last = (old == BPR - 1) ? 1 : 0;
    }
    __syncthreads();
    if (!sh_last) return;

    // ============ per-row selection (last block of this row) ============
    __threadfence();   // acquire: see all blocks' hist/accumulator writes

    const unsigned np_row = g_n_pos[row];
    const float    sp_row = g_sum_pos[row];
    const unsigned nm_row = g_n_mask[row];
    const float    st_row = g_sum_all[row];

    {
        unsigned cnt2[2]; float sum2[2];
        unsigned csum = 0u; float fsum = 0.f;
        #pragma unroll
        for (int k = 0; k < 2; k++) {
            unsigned long long v = g_hist[row][tid * 2 + k];
            cnt2[k] = (unsigned)(v >> CNT_SHIFT);
            sum2[k] = (float)(v & SUM_MASK) * INV_SUMSCALE;
            csum += cnt2[k]; fsum += sum2[k];
        }

        unsigned ci = csum; float fi = fsum;
        #pragma unroll
        for (int off = 1; off < 32; off <<= 1) {
            unsigned c2 = __shfl_down_sync(0xffffffffu, ci, off);
            float    f2 = __shfl_down_sync(0xffffffffu, fi, off);
            if (lane + off < 32) { ci += c2; fi += f2; }
        }
        if (lane == 0) { s_wc[wid] = ci; s_wf[wid] = fi; }
        if (tid == 0) sh_kept = 0.f;
        __syncthreads();

        if (tid == 0) {
            unsigned ca = 0u; float sa = 0.f;
            for (int w = (TPB / 32) - 1; w >= 0; w--) {
                s_wca[w] = ca; s_wfa[w] = sa;
                ca += s_wc[w]; sa += s_wf[w];
            }
            sh_nlow   = ca;
            sh_lowsum = sa;
        }
        __syncthreads();

        const unsigned count_low = sh_nlow;
        const float    lowsum    = sh_lowsum;
        const unsigned n_neg     = nm_row - np_row;
        const unsigned nh_row    = n_neg - count_low;
        const float    sh_row    = st_row - sp_row - lowsum;

        const unsigned avail = (K_ALL > np_row) ? (K_ALL - np_row) : 0u;
        const unsigned j     = (avail < n_neg) ? avail : n_neg;

        const int resolved = (j >= nh_row);
        const unsigned ju  = resolved ? (j - nh_row) : 0u;

        if (ju > 0u) {
            unsigned ca = s_wca[wid] + (ci - csum);
            float    sa = s_wfa[wid] + (fi - fsum);
            #pragma unroll
            for (int k = 1; k >= 0; k--) {
                unsigned c = cnt2[k];
                if (c && ca < ju && ca + c >= ju) {
                    float r    = (float)(ju - ca);
                    float mean = sum2[k] / (float)c;
                    sh_kept = sa + r * mean;
                }
                ca += c;
                sa += sum2[k];
            }
        }

        // cleanup this row for next graph replay
        #pragma unroll
        for (int k = 0; k < 2; k++) g_hist[row][tid * 2 + k] = 0ull;
        if (tid == 0) {
            g_sum_pos[row]  = 0.f;  g_n_pos[row]  = 0u;
            g_sum_all[row]  = 0.f;  g_n_mask[row] = 0u;
            g_row_done[row] = 0u;
        }
        __syncthreads();

        if (tid == 0) {
            if (resolved) {
                float kkeep = (float)(np_row + j);
                float kept  = sh_row + sh_kept;
                g_per[row] = (kkeep > 0.f)
                           ? (sp_row + kept) / fmaxf(kkeep, 1.f) : 0.f;
                g_need_fb[row] = 0;
            } else {
                g_need_fb[row] = 1;   // cold path: global-last resolves
            }
        }
    }

    // ============ elect global-last block ============
    __threadfence();
    if (tid == 0) {
        unsigned old = atomicAdd(&g_rows_done, 1u);
        sh_glast = (old == NROW - 1) ? 1 : 0;
    }
    __syncthreads();
    if (!sh_glast) return;

    __threadfence();   // acquire: see all rows' g_per / g_need_fb

    // O(1) hot-path epilogue: one batched flag-read round, then mean.
    if (tid == 0) {
        int any = 0;
        #pragma unroll
        for (int r = 0; r < NROW; r++) any |= g_need_fb[r];   // independent loads
        sh_fbany = any;
    }
    __syncthreads();

    if (!sh_fbany) {
        if (tid == 0) {
            g_rows_done = 0u;
            float tot = 0.f;
            #pragma unroll
            for (int r = 0; r < NROW; r++) tot += g_per[r];
            d_out[0] = tot * (1.f / (float)NROW);
        }
        return;
    }

    // ---------- cold fallback: full recompute for flagged rows ----------
    for (int r = 0; r < NROW; r++) {
        if (tid == 0) sh_fb = g_need_fb[r];
        __syncthreads();
        if (!sh_fb) continue;

        // zero global fallback histogram
        for (int i = tid; i < NBIN; i += TPB) g_fb_hist[i] = 0ull;
        __syncthreads();
        __threadfence_block();

        const float4* fxl = (const float4*)(logits  + (size_t)r * ROWN);
        const int4*   ftl = (const int4*)  (targets + (size_t)r * ROWN);
        const int4*   fml = (const int4*)  (mask    + (size_t)r * ROWN);

        float fsp = 0.f; unsigned fnp = 0u;
        for (int i = tid; i < N4; i += TPB) {
            float4 x4 = fxl[i]; int4 t4 = ftl[i]; int4 m4 = fml[i];
            float xs[4] = {x4.x, x4.y, x4.z, x4.w};
            int   ts[4] = {t4.x, t4.y, t4.z, t4.w};
            int   ms[4] = {m4.x, m4.y, m4.z, m4.w};
            #pragma unroll
            for (int k = 0; k < 4; k++) {
                float x = xs[k]; int t = ts[k]; int m = ms[k];
                float s = __logf(1.f + __expf(-fabsf(x)));
                float xf = __int_as_float(__float_as_int(x) ^ (t << 31));
                float bce = fmaxf(s + fmaxf(xf, 0.f), 0.f);
                if (m & t) { fsp += bce; fnp++; }
                if (m & (t ^ 1)) {
                    unsigned bin = __float_as_uint(bce) >> 21;
                    unsigned long long pk = (1ull << CNT_SHIFT)
                        | (unsigned long long)(unsigned)(bce * SUMSCALE + 0.5f);
                    atomicAdd(&g_fb_hist[bin], pk);
                }
            }
        }
        #pragma unroll
        for (int o = 16; o > 0; o >>= 1) {
            fsp += __shfl_down_sync(0xffffffffu, fsp, o);
            fnp += __shfl_down_sync(0xffffffffu, fnp, o);
        }
        if (lane == 0) { r_sp[wid] = fsp; r_np[wid] = fnp; }
        __syncthreads();
        __threadfence();

        unsigned cnt8[8]; float sum8[8];
        unsigned csum = 0u; float fsum = 0.f;
        #pragma unroll
        for (int k = 0; k < 8; k++) {
            unsigned long long v = g_fb_hist[tid * 8 + k];
            cnt8[k] = (unsigned)(v >> CNT_SHIFT);
            sum8[k] = (float)(v & SUM_MASK) * INV_SUMSCALE;
            csum += cnt8[k]; fsum += sum8[k];
        }
        unsigned ci = csum; float fi = fsum;
        #pragma unroll
        for (int off = 1; off < 32; off <<= 1) {
            unsigned c2 = __shfl_down_sync(0xffffffffu, ci, off);
            float    f2 = __shfl_down_sync(0xffffffffu, fi, off);
            if (lane + off < 32) { ci += c2; fi += f2; }
        }
        if (lane == 0) { s_wc[wid] = ci; s_wf[wid] = fi; }
        if (tid == 0) sh_kept = 0.f;
        __syncthreads();
        if (tid == 0) {
            unsigned ca = 0u; float sa = 0.f;
            for (int w = (TPB / 32) - 1; w >= 0; w--) {
                s_wca[w] = ca; s_wfa[w] = sa;
                ca += s_wc[w]; sa += s_wf[w];
            }
            sh_nlow = ca;   // total negatives
        }
        __syncthreads();

        __shared__ unsigned sh_np2;
        if (tid == 0) {
            float bsp = 0.f; unsigned bnp = 0u;
            #pragma unroll
            for (int w = 0; w < TPB / 32; w++) { bsp += r_sp[w]; bnp += r_np[w]; }
            r_sp[0] = bsp; sh_np2 = bnp;
        }
        __syncthreads();
        const unsigned npr   = sh_np2;
        const unsigned n_neg = sh_nlow;
        const unsigned avail = (K_ALL > npr) ? (K_ALL - npr) : 0u;
        const unsigned ju    = (avail < n_neg) ? avail : n_neg;

        if (ju > 0u) {
            unsigned ca = s_wca[wid] + (ci - csum);
            float    sa = s_wfa[wid] + (fi - fsum);
            #pragma unroll
            for (int k = 7; k >= 0; k--) {
                unsigned c = cnt8[k];
                if (c && ca < ju && ca + c >= ju) {
                    float rr   = (float)(ju - ca);
                    float mean = sum8[k] / (float)c;
                    sh_kept = sa + rr * mean;
                }
                ca += c;
                sa += sum8[k];
            }
        }
        __syncthreads();

        // re-zero fallback hist for next replay
        for (int i = tid; i < NBIN; i += TPB) g_fb_hist[i] = 0ull;

        if (tid == 0) {
            float kkeep = (float)(npr + ju);
            g_per[r] = (kkeep > 0.f)
                     ? (r_sp[0] + sh_kept) / fmaxf(kkeep, 1.f) : 0.f;
            g_need_fb[r] = 0;
        }
        __syncthreads();
    }

    if (tid == 0) {
        g_rows_done = 0u;
        float tot = 0.f;
        #pragma unroll
        for (int r = 0; r < NROW; r++) tot += g_per[r];
        d_out[0] = tot * (1.f / (float)NROW);
    }
}

// ---------------------------------------------------------------
extern "C" void kernel_launch(void* const* d_in, const int* in_sizes, int n_in,
                              void* d_out, int out_size)
{
    (void)in_sizes; (void)n_in; (void)out_size;
    const float* logits  = (const float*)d_in[0];
    const int*   targets = (const int*)d_in[1];
    const int*   mask    = (const int*)d_in[2];
    float*       out     = (float*)d_out;

    dim3 grid(BPR, NROW);
    ohem_fused<<<grid, TPB>>>(logits, targets, mask, out);
}

// round 16
// speedup vs baseline: 1.2771x; 1.0843x over previous
#include <cuda_runtime.h>

#define NROW 8
#define ROWN (1 << 20)          // elements per batch row
#define N4   (ROWN / 4)         // float4 count per row
#define NLOW 512                // low-bin histogram size (hot path)
#define PIVOT 0.125f            // bce < PIVOT -> histogram path (bin < 496)
#define NBIN 2048               // full bins (fallback path only)
#define BPR  114                // 912 blocks = 6/SM x 152 SMs, one wave
#define TPB  256
#define K_ALL 524288u           // max(1, int(N * 0.5))
#define SUMSCALE 4194304.0f     // 2^22 fixed-point scale for packed sums
#define INV_SUMSCALE 2.384185791015625e-7f   // 2^-22
#define CNT_SHIFT 44
#define SUM_MASK ((1ull << CNT_SHIFT) - 1ull)

// ---- global scratch (zero-initialized at load; tails restore zeros) ----
__device__ unsigned long long g_hist[NROW][NLOW];
__device__ unsigned long long g_fb_hist[NBIN];    // fallback only (cold)
__device__ float    g_sum_pos[NROW];
__device__ unsigned g_n_pos[NROW];
__device__ float    g_sum_all[NROW];   // sum of masked bce
__device__ unsigned g_n_mask[NROW];    // count of masked
__device__ unsigned g_row_done[NROW];
__device__ int      g_need_fb[NROW];
__device__ float    g_per[NROW];
__device__ unsigned g_rows_done;

// ---------------------------------------------------------------
// Single kernel. grid = (BPR, NROW), block = TPB.
// ---------------------------------------------------------------
__global__ __launch_bounds__(TPB, 6) void ohem_fused(
    const float* __restrict__ logits,
    const int*   __restrict__ targets,
    const int*   __restrict__ mask,
    float*       __restrict__ d_out)
{
    __shared__ unsigned long long s_hist[NLOW];
    __shared__ float    r_sp[TPB / 32], r_st[TPB / 32];
    __shared__ unsigned r_np[TPB / 32], r_nm[TPB / 32];
    __shared__ unsigned s_wc[TPB / 32], s_wca[TPB / 32];
    __shared__ float    s_wf[TPB / 32], s_wfa[TPB / 32];
    __shared__ float    sh_kept, sh_lowsum;
    __shared__ unsigned sh_nlow;
    __shared__ int      sh_last, sh_glast, sh_fbany, sh_fb;

    const int row  = blockIdx.y;
    const int tid  = threadIdx.x;
    const int lane = tid & 31;
    const int wid  = tid >> 5;

    #pragma unroll
    for (int i = tid; i < NLOW; i += TPB) s_hist[i] = 0ull;
    __syncthreads();

    const float4* xl = (const float4*)(logits  + (size_t)row * ROWN);
    const int4*   tl = (const int4*)  (targets + (size_t)row * ROWN);
    const int4*   ml = (const int4*)  (mask    + (size_t)row * ROWN);

    float    sp = 0.f, st = 0.f;
    unsigned np = 0u,  nm = 0u;

    const int stride = BPR * TPB;

    #pragma unroll 4
    for (int i = blockIdx.x * TPB + tid; i < N4; i += stride) {
        float4 x4 = __ldcs(&xl[i]);     // evict-first: zero-reuse stream
        int4   t4 = __ldcs(&tl[i]);
        int4   m4 = __ldcs(&ml[i]);

        float xs[4] = {x4.x, x4.y, x4.z, x4.w};
        int   ts[4] = {t4.x, t4.y, t4.z, t4.w};
        int   ms[4] = {m4.x, m4.y, m4.z, m4.w};

        #pragma unroll
        for (int k = 0; k < 4; k++) {
            float x = xs[k];
            int   t = ts[k];          // {0,1}
            int   m = ms[k];          // {0,1}
            float s = __logf(1.f + __expf(-fabsf(x)));
            float xf = __int_as_float(__float_as_int(x) ^ (t << 31));
            float bce = s + fmaxf(xf, 0.f);   // == max(x,0)-x*t+log1p(exp(-|x|))

            int is_pos = m & t;
            st += m ? bce : 0.f;              // masked total (predicated)
            nm += (unsigned)m;
            sp += is_pos ? bce : 0.f;
            np += (unsigned)is_pos;

            if ((m & (t ^ 1)) && (bce < PIVOT)) {   // low-loss negative: rare
                unsigned bin = __float_as_uint(bce) >> 21;    // < 496
                unsigned long long pk = (1ull << CNT_SHIFT)
                    | (unsigned long long)(unsigned)(bce * SUMSCALE + 0.5f);
                atomicAdd(&s_hist[bin], pk);
            }
        }
    }

    // block reduce sp/np/st/nm
    #pragma unroll
    for (int o = 16; o > 0; o >>= 1) {
        sp += __shfl_down_sync(0xffffffffu, sp, o);
        st += __shfl_down_sync(0xffffffffu, st, o);
        np += __shfl_down_sync(0xffffffffu, np, o);
        nm += __shfl_down_sync(0xffffffffu, nm, o);
    }
    if (lane == 0) { r_sp[wid] = sp; r_st[wid] = st; r_np[wid] = np; r_nm[wid] = nm; }
    __syncthreads();

    if (tid == 0) {
        float bsp = 0.f, bst = 0.f; unsigned bnp = 0u, bnm = 0u;
        #pragma unroll
        for (int w = 0; w < TPB / 32; w++) {
            bsp += r_sp[w]; bst += r_st[w]; bnp += r_np[w]; bnm += r_nm[w];
        }
        atomicAdd(&g_sum_pos[row], bsp);
        atomicAdd(&g_sum_all[row], bst);
        atomicAdd(&g_n_pos[row],   bnp);
        atomicAdd(&g_n_mask[row],  bnm);
    }

    // flush low histogram (sparse)
    for (int b = tid; b < NLOW; b += TPB) {
        unsigned long long v = s_hist[b];
        if (v) atomicAdd(&g_hist[row][b], v);
    }

    __threadfence();
    if (tid == 0) {
        unsigned old = atomicAdd(&g_row_done[row], 1u);
        sh_last = (old == BPR - 1) ? 1 : 0;
    }
    __syncthreads();
    if (!sh_last) return;

    // ============ per-row selection (last block of this row) ============
    __threadfence();   // acquire: see all blocks' hist/accumulator writes

    const unsigned np_row = g_n_pos[row];
    const float    sp_row = g_sum_pos[row];
    const unsigned nm_row = g_n_mask[row];
    const float    st_row = g_sum_all[row];

    {
        unsigned cnt2[2]; float sum2[2];
        unsigned csum = 0u; float fsum = 0.f;
        #pragma unroll
        for (int k = 0; k < 2; k++) {
            unsigned long long v = g_hist[row][tid * 2 + k];
            cnt2[k] = (unsigned)(v >> CNT_SHIFT);
            sum2[k] = (float)(v & SUM_MASK) * INV_SUMSCALE;
            csum += cnt2[k]; fsum += sum2[k];
        }

        unsigned ci = csum; float fi = fsum;
        #pragma unroll
        for (int off = 1; off < 32; off <<= 1) {
            unsigned c2 = __shfl_down_sync(0xffffffffu, ci, off);
            float    f2 = __shfl_down_sync(0xffffffffu, fi, off);
            if (lane + off < 32) { ci += c2; fi += f2; }
        }
        if (lane == 0) { s_wc[wid] = ci; s_wf[wid] = fi; }
        if (tid == 0) sh_kept = 0.f;
        __syncthreads();

        if (tid == 0) {
            unsigned ca = 0u; float sa = 0.f;
            for (int w = (TPB / 32) - 1; w >= 0; w--) {
                s_wca[w] = ca; s_wfa[w] = sa;
                ca += s_wc[w]; sa += s_wf[w];
            }
            sh_nlow   = ca;
            sh_lowsum = sa;
        }
        __syncthreads();

        const unsigned count_low = sh_nlow;
        const float    lowsum    = sh_lowsum;
        const unsigned n_neg     = nm_row - np_row;
        const unsigned nh_row    = n_neg - count_low;
        const float    sh_row    = st_row - sp_row - lowsum;

        const unsigned avail = (K_ALL > np_row) ? (K_ALL - np_row) : 0u;
        const unsigned j     = (avail < n_neg) ? avail : n_neg;

        const int resolved = (j >= nh_row);
        const unsigned ju  = resolved ? (j - nh_row) : 0u;

        if (ju > 0u) {
            unsigned ca = s_wca[wid] + (ci - csum);
            float    sa = s_wfa[wid] + (fi - fsum);
            #pragma unroll
            for (int k = 1; k >= 0; k--) {
                unsigned c = cnt2[k];
                if (c && ca < ju && ca + c >= ju) {
                    float r    = (float)(ju - ca);
                    float mean = sum2[k] / (float)c;
                    sh_kept = sa + r * mean;
                }
                ca += c;
                sa += sum2[k];
            }
        }

        // cleanup this row for next graph replay
        #pragma unroll
        for (int k = 0; k < 2; k++) g_hist[row][tid * 2 + k] = 0ull;
        if (tid == 0) {
            g_sum_pos[row]  = 0.f;  g_n_pos[row]  = 0u;
            g_sum_all[row]  = 0.f;  g_n_mask[row] = 0u;
            g_row_done[row] = 0u;
        }
        __syncthreads();

        if (tid == 0) {
            if (resolved) {
                float kkeep = (float)(np_row + j);
                float kept  = sh_row + sh_kept;
                g_per[row] = (kkeep > 0.f)
                           ? (sp_row + kept) / fmaxf(kkeep, 1.f) : 0.f;
                g_need_fb[row] = 0;
            } else {
                g_need_fb[row] = 1;   // cold path: global-last resolves
            }
        }
    }

    // ============ elect global-last block ============
    __threadfence();
    if (tid == 0) {
        unsigned old = atomicAdd(&g_rows_done, 1u);
        sh_glast = (old == NROW - 1) ? 1 : 0;
    }
    __syncthreads();
    if (!sh_glast) return;

    __threadfence();   // acquire: see all rows' g_per / g_need_fb

    // O(1) hot-path epilogue: one batched flag-read round, then mean.
    if (tid == 0) {
        int any = 0;
        #pragma unroll
        for (int r = 0; r < NROW; r++) any |= g_need_fb[r];   // independent loads
        sh_fbany = any;
    }
    __syncthreads();

    if (!sh_fbany) {
        if (tid == 0) {
            g_rows_done = 0u;
            float tot = 0.f;
            #pragma unroll
            for (int r = 0; r < NROW; r++) tot += g_per[r];
            d_out[0] = tot * (1.f / (float)NROW);
        }
        return;
    }

    // ---------- cold fallback: full recompute for flagged rows ----------
    for (int r = 0; r < NROW; r++) {
        if (tid == 0) sh_fb = g_need_fb[r];
        __syncthreads();
        if (!sh_fb) continue;

        // zero global fallback histogram
        for (int i = tid; i < NBIN; i += TPB) g_fb_hist[i] = 0ull;
        __syncthreads();
        __threadfence_block();

        const float4* fxl = (const float4*)(logits  + (size_t)r * ROWN);
        const int4*   ftl = (const int4*)  (targets + (size_t)r * ROWN);
        const int4*   fml = (const int4*)  (mask    + (size_t)r * ROWN);

        float fsp = 0.f; unsigned fnp = 0u;
        for (int i = tid; i < N4; i += TPB) {
            float4 x4 = fxl[i]; int4 t4 = ftl[i]; int4 m4 = fml[i];
            float xs[4] = {x4.x, x4.y, x4.z, x4.w};
            int   ts[4] = {t4.x, t4.y, t4.z, t4.w};
            int   ms[4] = {m4.x, m4.y, m4.z, m4.w};
            #pragma unroll
            for (int k = 0; k < 4; k++) {
                float x = xs[k]; int t = ts[k]; int m = ms[k];
                float s = __logf(1.f + __expf(-fabsf(x)));
                float xf = __int_as_float(__float_as_int(x) ^ (t << 31));
                float bce = fmaxf(s + fmaxf(xf, 0.f), 0.f);
                if (m & t) { fsp += bce; fnp++; }
                if (m & (t ^ 1)) {
                    unsigned bin = __float_as_uint(bce) >> 21;
                    unsigned long long pk = (1ull << CNT_SHIFT)
                        | (unsigned long long)(unsigned)(bce * SUMSCALE + 0.5f);
                    atomicAdd(&g_fb_hist[bin], pk);
                }
            }
        }
        #pragma unroll
        for (int o = 16; o > 0; o >>= 1) {
            fsp += __shfl_down_sync(0xffffffffu, fsp, o);
            fnp += __shfl_down_sync(0xffffffffu, fnp, o);
        }
        if (lane == 0) { r_sp[wid] = fsp; r_np[wid] = fnp; }
        __syncthreads();
        __threadfence();

        unsigned cnt8[8]; float sum8[8];
        unsigned csum = 0u; float fsum = 0.f;
        #pragma unroll
        for (int k = 0; k < 8; k++) {
            unsigned long long v = g_fb_hist[tid * 8 + k];
            cnt8[k] = (unsigned)(v >> CNT_SHIFT);
            sum8[k] = (float)(v & SUM_MASK) * INV_SUMSCALE;
            csum += cnt8[k]; fsum += sum8[k];
        }
        unsigned ci = csum; float fi = fsum;
        #pragma unroll
        for (int off = 1; off < 32; off <<= 1) {
            unsigned c2 = __shfl_down_sync(0xffffffffu, ci, off);
            float    f2 = __shfl_down_sync(0xffffffffu, fi, off);
            if (lane + off < 32) { ci += c2; fi += f2; }
        }
        if (lane == 0) { s_wc[wid] = ci; s_wf[wid] = fi; }
        if (tid == 0) sh_kept = 0.f;
        __syncthreads();
        if (tid == 0) {
            unsigned ca = 0u; float sa = 0.f;
            for (int w = (TPB / 32) - 1; w >= 0; w--) {
                s_wca[w] = ca; s_wfa[w] = sa;
                ca += s_wc[w]; sa += s_wf[w];
            }
            sh_nlow = ca;   // total negatives
        }
        __syncthreads();

        __shared__ unsigned sh_np2;
        if (tid == 0) {
            float bsp = 0.f; unsigned bnp = 0u;
            #pragma unroll
            for (int w = 0; w < TPB / 32; w++) { bsp += r_sp[w]; bnp += r_np[w]; }
            r_sp[0] = bsp; sh_np2 = bnp;
        }
        __syncthreads();
        const unsigned npr   = sh_np2;
        const unsigned n_neg = sh_nlow;
        const unsigned avail = (K_ALL > npr) ? (K_ALL - npr) : 0u;
        const unsigned ju    = (avail < n_neg) ? avail : n_neg;

        if (ju > 0u) {
            unsigned ca = s_wca[wid] + (ci - csum);
            float    sa = s_wfa[wid] + (fi - fsum);
            #pragma unroll
            for (int k = 7; k >= 0; k--) {
                unsigned c = cnt8[k];
                if (c && ca < ju && ca + c >= ju) {
                    float rr   = (float)(ju - ca);
                    float mean = sum8[k] / (float)c;
                    sh_kept = sa + rr * mean;
                }
                ca += c;
                sa += sum8[k];
            }
        }
        __syncthreads();

        // re-zero fallback hist for next replay
        for (int i = tid; i < NBIN; i += TPB) g_fb_hist[i] = 0ull;

        if (tid == 0) {
            float kkeep = (float)(npr + ju);
            g_per[r] = (kkeep > 0.f)
                     ? (r_sp[0] + sh_kept) / fmaxf(kkeep, 1.f) : 0.f;
            g_need_fb[r] = 0;
        }
        __syncthreads();
    }

    if (tid == 0) {
        g_rows_done = 0u;
        float tot = 0.f;
        #pragma unroll
        for (int r = 0; r < NROW; r++) tot += g_per[r];
        d_out[0] = tot * (1.f / (float)NROW);
    }
}

// ---------------------------------------------------------------
extern "C" void kernel_launch(void* const* d_in, const int* in_sizes, int n_in,
                              void* d_out, int out_size)
{
    (void)in_sizes; (void)n_in; (void)out_size;
    const float* logits  = (const float*)d_in[0];
    const int*   targets = (const int*)d_in[1];
    const int*   mask    = (const int*)d_in[2];
    float*       out     = (float*)d_out;

    dim3 grid(BPR, NROW);
    ohem_fused<<<grid, TPB>>>(logits, targets, mask, out);
}